// round 7
// baseline (speedup 1.0000x reference)
#include <cuda_runtime.h>
#include <cfloat>

// RelationalCritic: B=2048, N=32, F=64, E=8, H=128, NA=4, NACT=16
#define Bn 2048

__device__ float g_pooled[(size_t)Bn * 128];

// ---- f32x2 packed-FMA helpers (B300 sm_103a) ------------------------------
__device__ __forceinline__ unsigned long long pk2(float x) {
    unsigned long long r; asm("mov.b64 %0, {%1, %1};" : "=l"(r) : "f"(x)); return r;
}
__device__ __forceinline__ unsigned long long pk2f2(float lo, float hi) {
    unsigned long long r; asm("mov.b64 %0, {%1, %2};" : "=l"(r) : "f"(lo), "f"(hi)); return r;
}
__device__ __forceinline__ void upk2(unsigned long long v, float& lo, float& hi) {
    asm("mov.b64 {%0, %1}, %2;" : "=f"(lo), "=f"(hi) : "l"(v));
}
__device__ __forceinline__ void ffma2(unsigned long long& d, unsigned long long a,
                                      unsigned long long b) {
    asm("fma.rn.f32x2 %0, %1, %2, %0;" : "+l"(d) : "l"(a), "l"(b));
}

// ---------------------------------------------------------------------------
// Fused kernel: embed -> per-relation (aggregate + GEMM-accumulate) -> root
// pass -> bias/relu/max-pool. One block = 4 batches = 128 rows.
// smem: sX[128][132] x, sY[128][132] ybar (also staging), sW[128][128] weights
// Microtile: thread (tr=t>>4, tc=t&15) owns rows {tr+16q}, cols tc*8..+7.
// ---------------------------------------------------------------------------
__global__ __launch_bounds__(256, 1) void k_main(
    const float* __restrict__ unary, const int* __restrict__ binary,
    const float* __restrict__ We, const float* __restrict__ be,
    const float* __restrict__ Wrel, const float* __restrict__ Wroot,
    const float* __restrict__ brel, float* __restrict__ pooled)
{
    extern __shared__ float sm[];
    float* sX = sm;                       // 128*132
    float* sY = sm + 16896;               // 128*132
    float* sW = sm + 33792;               // 128*128
    unsigned* adj = (unsigned*)(sm + 50176);  // [4][8][32]

    const int t  = threadIdx.x;
    const int b0 = blockIdx.x * 4;
    const int tr = t >> 4;                // 0..15
    const int tc = t & 15;                // 0..15
    const int c0 = tc * 8;

    // --- stage We -> sW, unary -> sY (stride 68), build adjacency masks ----
    {
        const float4* s = (const float4*)We;
        float4* d = (float4*)sW;
        for (int i = t; i < 2048; i += 256) d[i] = s[i];
    }
    {
        const float4* s = (const float4*)(unary + (size_t)b0 * 32 * 64);
        for (int i = t; i < 2048; i += 256) {
            int row = i >> 4, q4 = i & 15;
            *(float4*)(sY + row * 68 + q4 * 4) = s[i];
        }
    }
    #pragma unroll
    for (int lb = 0; lb < 4; lb++) {
        const int* bb = binary + (size_t)(b0 + lb) * 8192;
        unsigned m = 0;
        #pragma unroll
        for (int i = 0; i < 32; i++)
            m |= ((unsigned)(bb[i * 256 + t] != 0)) << i;
        adj[lb * 256 + (t & 7) * 32 + (t >> 3)] = m;
    }
    __syncthreads();

    unsigned long long acc[8][4];

    // --- embed: x = unary @ We + be  (K=64) --------------------------------
    #pragma unroll
    for (int q = 0; q < 8; q++)
        #pragma unroll
        for (int cp = 0; cp < 4; cp++)
            acc[q][cp] = pk2f2(be[c0 + cp * 2], be[c0 + cp * 2 + 1]);
    #pragma unroll 4
    for (int k = 0; k < 64; k++) {
        const ulonglong2 bA = *(const ulonglong2*)(sW + k * 128 + c0);
        const ulonglong2 bB = *(const ulonglong2*)(sW + k * 128 + c0 + 4);
        #pragma unroll
        for (int q = 0; q < 8; q++) {
            const unsigned long long a2 = pk2(sY[(tr + 16 * q) * 68 + k]);
            ffma2(acc[q][0], a2, bA.x); ffma2(acc[q][1], a2, bA.y);
            ffma2(acc[q][2], a2, bB.x); ffma2(acc[q][3], a2, bB.y);
        }
    }
    #pragma unroll
    for (int q = 0; q < 8; q++) {
        float* dst = sX + (tr + 16 * q) * 132 + c0;
        #pragma unroll
        for (int cp = 0; cp < 4; cp++)
            *(unsigned long long*)(dst + cp * 2) = acc[q][cp];
    }
    __syncthreads();

    // --- main loop: h = sum_e ybar_e @ Wrel[e] + x @ Wroot + brel ----------
    const int w = t >> 5, lane = t & 31;
    #pragma unroll
    for (int q = 0; q < 8; q++)
        #pragma unroll
        for (int cp = 0; cp < 4; cp++)
            acc[q][cp] = pk2f2(brel[c0 + cp * 2], brel[c0 + cp * 2 + 1]);

    for (int pass = 0; pass < 9; pass++) {
        if (pass) __syncthreads();   // previous GEMM readers done
        {
            const float4* s = (const float4*)(pass < 8 ? Wrel + (size_t)pass * 16384
                                                       : Wroot);
            float4* d = (float4*)sW;
            for (int i = t; i < 4096; i += 256) d[i] = s[i];
        }
        if (pass < 8) {
            // ybar for relation e=pass: warp per (lb,j), lane owns 4 d's
            for (int p = w; p < 128; p += 8) {
                const int lb = p >> 5, j = p & 31;
                const unsigned m = adj[lb * 256 + pass * 32 + j];
                const float inv = m ? 1.0f / (float)__popc(m) : 0.0f;
                float ax = 0.f, ay = 0.f, az = 0.f, aw = 0.f;
                unsigned mm = m;
                while (mm) {
                    const int i = __ffs(mm) - 1; mm &= mm - 1;
                    const float4 v = *(const float4*)(sX + (lb * 32 + i) * 132 + lane * 4);
                    ax += v.x; ay += v.y; az += v.z; aw += v.w;
                }
                *(float4*)(sY + p * 132 + lane * 4) =
                    make_float4(ax * inv, ay * inv, az * inv, aw * inv);
            }
        }
        __syncthreads();
        const float* A = (pass < 8) ? sY : sX;
        #pragma unroll 4
        for (int k = 0; k < 128; k++) {
            const ulonglong2 bA = *(const ulonglong2*)(sW + k * 128 + c0);
            const ulonglong2 bB = *(const ulonglong2*)(sW + k * 128 + c0 + 4);
            #pragma unroll
            for (int q = 0; q < 8; q++) {
                const unsigned long long a2 = pk2(A[(tr + 16 * q) * 132 + k]);
                ffma2(acc[q][0], a2, bA.x); ffma2(acc[q][1], a2, bA.y);
                ffma2(acc[q][2], a2, bB.x); ffma2(acc[q][3], a2, bB.y);
            }
        }
    }

    // --- epilogue: relu + max over the 32 nodes of each local batch --------
    float pm[4][8];
    #pragma unroll
    for (int lb = 0; lb < 4; lb++)
        #pragma unroll
        for (int c = 0; c < 8; c++) pm[lb][c] = 0.0f;
    #pragma unroll
    for (int q = 0; q < 8; q++) {
        const int lb = q >> 1;        // rows tr+16q: q pairs map to batches
        #pragma unroll
        for (int cp = 0; cp < 4; cp++) {
            float lo, hi; upk2(acc[q][cp], lo, hi);
            pm[lb][cp * 2]     = fmaxf(pm[lb][cp * 2], lo);
            pm[lb][cp * 2 + 1] = fmaxf(pm[lb][cp * 2 + 1], hi);
        }
    }
    __syncthreads();
    float* sRed = sY;                 // [16 tr][stride 529][lb*132+c]
    #pragma unroll
    for (int lb = 0; lb < 4; lb++)
        #pragma unroll
        for (int c = 0; c < 8; c++)
            sRed[tr * 529 + lb * 132 + c0 + c] = pm[lb][c];
    __syncthreads();
    for (int idx = t; idx < 512; idx += 256) {
        const int lb = idx >> 7, c = idx & 127;
        float mx = sRed[lb * 132 + c];
        #pragma unroll
        for (int r = 1; r < 16; r++) mx = fmaxf(mx, sRed[r * 529 + lb * 132 + c]);
        pooled[(size_t)(b0 + lb) * 128 + c] = mx;
    }
}

// ---------------------------------------------------------------------------
// Heads: z = leaky(pooled @ W1[a] + b1[a]); q = z @ W2[a][:,argmax(actions)]
// Block = (agent, 64-batch tile). GEMM microtile 8x4 per thread.
// ---------------------------------------------------------------------------
__global__ __launch_bounds__(256, 1) void k_heads(
    const float* __restrict__ actions, const float* __restrict__ W1,
    const float* __restrict__ b1, const float* __restrict__ W2,
    const float* __restrict__ b2, const float* __restrict__ pooled,
    float* __restrict__ out)
{
    extern __shared__ float sm[];
    float* sP  = sm;              // 64 x 132 (pooled rows, later z rows)
    float* sW1 = sm + 64 * 132;   // 128 x 128

    const int t = threadIdx.x;
    const int a = blockIdx.x >> 5, tile = blockIdx.x & 31;
    const int r0 = tile * 64;

    {
        const float4* s = (const float4*)(pooled + (size_t)r0 * 128);
        for (int i = t; i < 2048; i += 256) {
            int row = i >> 5, q4 = i & 31;
            *(float4*)(sP + row * 132 + q4 * 4) = s[i];
        }
        const float4* s2 = (const float4*)(W1 + (size_t)a * 16384);
        float4* d = (float4*)sW1;
        for (int i = t; i < 4096; i += 256) d[i] = s2[i];
    }
    __syncthreads();

    const int tr = t >> 5, tc = t & 31;   // rows tr+8q, cols tc*4..+3
    unsigned long long acc[8][2];
    #pragma unroll
    for (int q = 0; q < 8; q++) {
        acc[q][0] = pk2f2(b1[a * 128 + tc * 4],     b1[a * 128 + tc * 4 + 1]);
        acc[q][1] = pk2f2(b1[a * 128 + tc * 4 + 2], b1[a * 128 + tc * 4 + 3]);
    }
    #pragma unroll 4
    for (int k = 0; k < 128; k++) {
        const ulonglong2 bv = *(const ulonglong2*)(sW1 + k * 128 + tc * 4);
        #pragma unroll
        for (int q = 0; q < 8; q++) {
            const unsigned long long a2 = pk2(sP[(tr + 8 * q) * 132 + k]);
            ffma2(acc[q][0], a2, bv.x); ffma2(acc[q][1], a2, bv.y);
        }
    }
    __syncthreads();
    #pragma unroll
    for (int q = 0; q < 8; q++) {
        float z[4];
        upk2(acc[q][0], z[0], z[1]); upk2(acc[q][1], z[2], z[3]);
        float* d = sP + (tr + 8 * q) * 132 + tc * 4;
        #pragma unroll
        for (int c = 0; c < 4; c++)
            d[c] = z[c] > 0.f ? z[c] : 0.01f * z[c];
    }
    __syncthreads();

    const int wv = t >> 5, ln = t & 31;
    for (int rr = wv; rr < 64; rr += 8) {
        const int batch = r0 + rr;
        // argmax over 16 actions (all 32 lanes converge; lower index on tie)
        float av = (ln < 16) ? actions[((size_t)a * Bn + batch) * 16 + ln] : -FLT_MAX;
        int ai = ln;
        #pragma unroll
        for (int off = 16; off; off >>= 1) {
            const float ov = __shfl_xor_sync(0xffffffffu, av, off);
            const int   oi = __shfl_xor_sync(0xffffffffu, ai, off);
            if (ov > av || (ov == av && oi < ai)) { av = ov; ai = oi; }
        }
        float part = 0.f;
        #pragma unroll
        for (int hq = 0; hq < 4; hq++) {
            const int h = ln * 4 + hq;
            part += sP[rr * 132 + h] * W2[((size_t)a * 128 + h) * 16 + ai];
        }
        #pragma unroll
        for (int off = 16; off; off >>= 1)
            part += __shfl_xor_sync(0xffffffffu, part, off);
        if (ln == 0) out[(size_t)a * Bn + batch] = part + b2[a * 16 + ai];
    }
}

// ---------------------------------------------------------------------------
extern "C" void kernel_launch(void* const* d_in, const int* in_sizes, int n_in,
                              void* d_out, int out_size)
{
    const float* unary   = (const float*)d_in[0];
    const int*   binary  = (const int*)  d_in[1];
    const float* actions = (const float*)d_in[2];
    const float* We      = (const float*)d_in[3];
    const float* be      = (const float*)d_in[4];
    const float* Wrel    = (const float*)d_in[5];
    const float* Wroot   = (const float*)d_in[6];
    const float* brel    = (const float*)d_in[7];
    const float* W1      = (const float*)d_in[8];
    const float* b1      = (const float*)d_in[9];
    const float* W2      = (const float*)d_in[10];
    const float* b2      = (const float*)d_in[11];
    float* out = (float*)d_out;

    float* pooled = nullptr;
    cudaGetSymbolAddress((void**)&pooled, g_pooled);

    const int smem_main  = (16896 + 16896 + 16384 + 1024) * 4;  // 204800 B
    const int smem_heads = (64 * 132 + 16384) * 4;              // 99328 B
    cudaFuncSetAttribute(k_main,  cudaFuncAttributeMaxDynamicSharedMemorySize, smem_main);
    cudaFuncSetAttribute(k_heads, cudaFuncAttributeMaxDynamicSharedMemorySize, smem_heads);

    k_main<<<512, 256, smem_main>>>(unary, binary, We, be, Wrel, Wroot, brel, pooled);
    k_heads<<<128, 256, smem_heads>>>(actions, W1, b1, W2, b2, pooled, out);
}